// round 2
// baseline (speedup 1.0000x reference)
#include <cuda_runtime.h>
#include <math.h>
#include <stddef.h>

#define EPSR 1e-8f
// 1/sqrt(1 + 1e-5)
#define BN_SCALE 0.99999500003749969f
#define LOG2PI 1.8378770664093454836f

// ---------------------------------------------------------------------------
// Scratch buffers (device globals; no allocation allowed)
// ---------------------------------------------------------------------------
__device__ float g_buf1 [32*256*14*14];  // conv1+bn out
__device__ float g_bufA [32*16*12*12];   // a (sigmoid(bn(conva)))
__device__ float g_bufP [32*256*12*12];  // pose (bn(convp))
__device__ float g_bufA2[32*16*6*6];     // EM1 a out
__device__ float g_bufP2[32*256*6*6];    // EM1 pose out (bnc1 fused)
__device__ float g_bufA3[32*16*6*6];     // EM2 a out
__device__ float g_bufP3[32*256*6*6];    // EM2 pose out (bnc2 fused)
__device__ float g_bufFC[32*25*10];      // EM3 a out per (b, l)

// ---------------------------------------------------------------------------
// conv1: x(32,3,32,32) * w(256,3,5,5) stride2 VALID -> (32,256,14,14), + bn
// ---------------------------------------------------------------------------
__global__ void conv1_kernel(const float* __restrict__ x,
                             const float* __restrict__ w,
                             const float* __restrict__ g,
                             const float* __restrict__ b,
                             float* __restrict__ out)
{
    __shared__ float sIn[3*32*33];
    const int n = blockIdx.x, cot = blockIdx.y;
    const int tid = threadIdx.x;

    for (int idx = tid; idx < 3*32*32; idx += 224) {
        int ci = idx >> 10, rem = idx & 1023, r = rem >> 5, c = rem & 31;
        sIn[(ci*32 + r)*33 + c] = x[n*3072 + idx];
    }
    __syncthreads();

    const int co_l = tid / 14, oy = tid % 14;
    const int co = cot*16 + co_l;

    float acc[14];
#pragma unroll
    for (int i = 0; i < 14; i++) acc[i] = 0.f;

    const float* wp = w + co*75;
#pragma unroll
    for (int ci = 0; ci < 3; ci++) {
#pragma unroll
        for (int kh = 0; kh < 5; kh++) {
            const float* row = sIn + (ci*32 + oy*2 + kh)*33;
#pragma unroll
            for (int kw = 0; kw < 5; kw++) {
                float wv = wp[(ci*5 + kh)*5 + kw];
#pragma unroll
                for (int ox = 0; ox < 14; ox++)
                    acc[ox] = fmaf(wv, row[ox*2 + kw], acc[ox]);
            }
        }
    }
    const float sc = BN_SCALE * g[co], bi = b[co];
    float* op = out + (((size_t)n*256 + co)*14 + oy)*14;
#pragma unroll
    for (int ox = 0; ox < 14; ox++) op[ox] = acc[ox]*sc + bi;
}

// ---------------------------------------------------------------------------
// 3x3 conv over buf1 (N,CI=256,14,14) -> (N,CO,12,12), + bn (+sigmoid)
// ---------------------------------------------------------------------------
template<bool SIG>
__global__ void conv3_kernel(const float* __restrict__ in,
                             const float* __restrict__ w,
                             const float* __restrict__ g,
                             const float* __restrict__ bb,
                             float* __restrict__ out,
                             int CI, int CO)
{
    extern __shared__ float sIn[];   // 64*196
    const int n = blockIdx.x;
    const int tid = threadIdx.x;
    const int co_l = tid / 12, oy = tid % 12;
    const int co = blockIdx.y*16 + co_l;

    float acc[12];
#pragma unroll
    for (int i = 0; i < 12; i++) acc[i] = 0.f;

    for (int ci0 = 0; ci0 < CI; ci0 += 64) {
        __syncthreads();
        for (int idx = tid; idx < 64*196; idx += 192)
            sIn[idx] = in[((size_t)n*CI + ci0)*196 + idx];
        __syncthreads();

        for (int c = 0; c < 64; c++) {
            const float* wp = w + ((size_t)co*CI + ci0 + c)*9;
            float w9[9];
#pragma unroll
            for (int i = 0; i < 9; i++) w9[i] = wp[i];
#pragma unroll
            for (int kh = 0; kh < 3; kh++) {
                const float* row = sIn + (c*14 + oy + kh)*14;
                float rv[14];
#pragma unroll
                for (int i = 0; i < 14; i++) rv[i] = row[i];
#pragma unroll
                for (int kw = 0; kw < 3; kw++) {
                    float wv = w9[kh*3 + kw];
#pragma unroll
                    for (int ox = 0; ox < 12; ox++)
                        acc[ox] = fmaf(wv, rv[ox + kw], acc[ox]);
                }
            }
        }
    }
    const float sc = BN_SCALE * g[co], bi = bb[co];
    float* op = out + (((size_t)n*CO + co)*12 + oy)*12;
#pragma unroll
    for (int ox = 0; ox < 12; ox++) {
        float v = acc[ox]*sc + bi;
        if (SIG) v = 1.0f / (1.0f + expf(-v));
        op[ox] = v;
    }
}

// ---------------------------------------------------------------------------
// EM routing v2: one CTA per (n, l). 1024 threads. Votes in smem.
//   Phase E: warp-per-k, lane=(h,j), float4 vote loads + shuffle softmax.
//   Phases B/C: k-split over all threads. Phase A: warp-per-j.
// ---------------------------------------------------------------------------
template<int A_, int PS, int BB, int KS, int STR, int PD, int IH, int OH,
         int KSPLIT, bool WPOSE, bool FC>
__global__ __launch_bounds__(1024, 1)
void em_kernel(const float* __restrict__ aIn,
               const float* __restrict__ poseIn,
               const float* __restrict__ Wm,    // (KS*KS*A_, BB, 4,4)
               const float* __restrict__ bu,
               const float* __restrict__ ba,
               const float* __restrict__ bng,
               const float* __restrict__ bnb,
               float* __restrict__ aOut,
               float* __restrict__ poseOut)
{
    constexpr int NT   = 1024;
    constexpr int KK   = KS*KS;
    constexpr int KKA  = KK*A_;
    constexpr int BBPS = BB*PS;
    constexpr int VST  = BBPS + 4;   // mult of 4, VST%32==4 -> conflict-free f4
    constexpr int RST  = BB + 1;
    constexpr int SPS  = PS + 1;
    constexpr int CH   = (KKA + KSPLIT - 1) / KSPLIT;

    extern __shared__ float sm[];
    float* sv   = sm;                       // KKA*VST  (16B aligned)
    float* smu  = sv   + KKA*VST;           // BBPS
    float* ssg  = smu  + BBPS;              // BBPS   (holds 1/(2 sigma))
    float* pb   = ssg  + BBPS;              // KSPLIT*BBPS partials / logs
    float* spt  = pb   + KSPLIT*BBPS;       // KKA*SPS
    float* sr   = spt  + KKA*SPS;           // KKA*RST
    float* sa   = sr   + KKA*RST;           // KKA
    float* srs  = sa   + KKA;               // BB
    float* sinv = srs  + BB;                // BB
    float* sao  = sinv + BB;                // BB
    float* sbia = sao  + BB;                // BB

    const int lidx = blockIdx.x;
    const int oy = lidx / OH, ox = lidx % OH;
    const int n  = blockIdx.y;
    const int tid  = threadIdx.x;
    const int wid  = tid >> 5;
    const int lane = tid & 31;

    // ---- Phase 0a: gather pose patch + a_in (zero-padded) ----
    for (int t = tid; t < KKA*PS; t += NT) {
        const int k = t / PS, p = t % PS;
        const int kk = k / A_, ai = k % A_;
        const int ki = kk / KS, kj = kk % KS;
        const int iy = oy*STR + ki - PD, ix = ox*STR + kj - PD;
        float v = 0.f;
        if (iy >= 0 && iy < IH && ix >= 0 && ix < IH)
            v = poseIn[(((size_t)n*A_*PS + ai*PS + p)*IH + iy)*IH + ix];
        spt[k*SPS + p] = v;
    }
    for (int k = tid; k < KKA; k += NT) {
        const int kk = k / A_, ai = k % A_;
        const int ki = kk / KS, kj = kk % KS;
        const int iy = oy*STR + ki - PD, ix = ox*STR + kj - PD;
        float v = 0.f;
        if (iy >= 0 && iy < IH && ix >= 0 && ix < IH)
            v = aIn[(((size_t)n*A_ + ai)*IH + iy)*IH + ix];
        sa[k] = v;
    }
    __syncthreads();

    // ---- Phase 0b: votes v[k][j] = pose4x4 @ W[k][j]; init r = 1/BB ----
    for (int t = tid; t < KKA*BB; t += NT) {
        const int k = t / BB, j = t % BB;
        const float* pm = spt + k*SPS;
        const float* wj = Wm + ((size_t)k*BB + j)*16;
        float* vk = sv + k*VST + j*PS;
#pragma unroll
        for (int xi = 0; xi < 4; xi++) {
            float r0=0.f, r1=0.f, r2=0.f, r3=0.f;
#pragma unroll
            for (int y = 0; y < 4; y++) {
                float a = pm[xi*4 + y];
                r0 = fmaf(a, wj[y*4+0], r0);
                r1 = fmaf(a, wj[y*4+1], r1);
                r2 = fmaf(a, wj[y*4+2], r2);
                r3 = fmaf(a, wj[y*4+3], r3);
            }
            float4 o; o.x=r0; o.y=r1; o.z=r2; o.w=r3;
            *(float4*)(vk + xi*4) = o;
        }
        sr[k*RST + j] = 1.0f / (float)BB;
    }
    __syncthreads();

    float p95 = 1.0f;
    for (int it = 0; it < 3; it++) {
        p95 *= 0.95f;
        const float lam = 0.01f * (1.0f - p95);

        // A: r_sum[j] = sum_k r*a  (warp-per-j, shuffle reduce)
        if (wid < BB) {
            float s = 0.f;
            for (int k = lane; k < KKA; k += 32)
                s = fmaf(sr[k*RST + wid], sa[k], s);
#pragma unroll
            for (int d = 16; d; d >>= 1)
                s += __shfl_xor_sync(0xffffffffu, s, d);
            if (lane == 0) { srs[wid] = s; sinv[wid] = 1.0f/(s + EPSR); }
        }
        __syncthreads();

        // A2: coeff in place
        for (int t = tid; t < KKA*BB; t += NT) {
            const int k = t / BB, j = t % BB;
            sr[k*RST + j] *= sa[k] * sinv[j];
        }
        __syncthreads();

        // B: mu partials (k-split)
        if (tid < KSPLIT*BBPS) {
            const int h = tid / BBPS, r = tid % BBPS, j = r / PS;
            const int k0 = h*CH, k1 = (k0 + CH < KKA) ? k0 + CH : KKA;
            float m = 0.f;
            for (int k = k0; k < k1; k++)
                m = fmaf(sr[k*RST + j], sv[k*VST + r], m);
            pb[tid] = m;
        }
        __syncthreads();
        if (tid < BBPS) {
            float m = 0.f;
#pragma unroll
            for (int h = 0; h < KSPLIT; h++) m += pb[h*BBPS + tid];
            smu[tid] = m;
        }
        __syncthreads();

        // C: sigma partials (k-split)
        if (tid < KSPLIT*BBPS) {
            const int h = tid / BBPS, r = tid % BBPS, j = r / PS;
            const int k0 = h*CH, k1 = (k0 + CH < KKA) ? k0 + CH : KKA;
            const float mu = smu[r];
            float s = 0.f;
            for (int k = k0; k < k1; k++) {
                float d = sv[k*VST + r] - mu;
                s = fmaf(sr[k*RST + j], d*d, s);
            }
            pb[tid] = s;
        }
        __syncthreads();
        if (tid < BBPS) {
            float s = EPSR;
#pragma unroll
            for (int h = 0; h < KSPLIT; h++) s += pb[h*BBPS + tid];
            pb[tid]  = __logf(s);       // log(sigma)
            ssg[tid] = 0.5f / s;        // 1/(2 sigma)
        }
        __syncthreads();

        // D: cost, a_out, softmax bias per j
        if (tid < BB) {
            float sl = 0.f;
#pragma unroll
            for (int p = 0; p < PS; p++) sl += pb[tid*PS + p];
            const float cost = ((float)PS*bu[tid] + 0.5f*sl) * srs[tid];
            const float ao = 1.0f / (1.0f + __expf(-lam*(ba[tid] - cost)));
            sao[tid]  = ao;
            sbia[tid] = -0.5f*((float)PS*LOG2PI + sl) + __logf(ao + EPSR);
        }
        __syncthreads();

        // E: new r  (warp-per-k; lane = h*16 + j)
        if (it < 2) {
            const int j = lane & 15, h = lane >> 4;
            const bool act = (j < BB);
            for (int k = wid; k < KKA; k += NT/32) {
                float q = 0.f;
                if (act) {
                    const float4* vv = (const float4*)(sv + k*VST + j*PS + h*8);
                    const float4* mm = (const float4*)(smu + j*PS + h*8);
                    const float4* gg = (const float4*)(ssg + j*PS + h*8);
                    float4 v0 = vv[0], v1 = vv[1];
                    float4 m0 = mm[0], m1 = mm[1];
                    float4 g0 = gg[0], g1 = gg[1];
                    float d;
                    d = v0.x-m0.x; q = fmaf(d*d, g0.x, q);
                    d = v0.y-m0.y; q = fmaf(d*d, g0.y, q);
                    d = v0.z-m0.z; q = fmaf(d*d, g0.z, q);
                    d = v0.w-m0.w; q = fmaf(d*d, g0.w, q);
                    d = v1.x-m1.x; q = fmaf(d*d, g1.x, q);
                    d = v1.y-m1.y; q = fmaf(d*d, g1.y, q);
                    d = v1.z-m1.z; q = fmaf(d*d, g1.z, q);
                    d = v1.w-m1.w; q = fmaf(d*d, g1.w, q);
                }
                q += __shfl_xor_sync(0xffffffffu, q, 16);
                float lnp = act ? sbia[j] - q : -1e30f;
                float mx = lnp;
#pragma unroll
                for (int d = 8; d; d >>= 1)
                    mx = fmaxf(mx, __shfl_xor_sync(0xffffffffu, mx, d));
                float e = act ? __expf(lnp - mx) : 0.f;
                float se = e;
#pragma unroll
                for (int d = 8; d; d >>= 1)
                    se += __shfl_xor_sync(0xffffffffu, se, d);
                if (h == 0 && act) sr[k*RST + j] = e / se;
            }
            __syncthreads();
        }
    }
    __syncthreads();

    // Outputs
    if (WPOSE) {
        for (int t = tid; t < BBPS; t += NT) {
            poseOut[(((size_t)n*BBPS + t)*OH + oy)*OH + ox] =
                smu[t]*BN_SCALE*bng[t] + bnb[t];
        }
    }
    if (tid < BB) {
        if (FC)
            aOut[((size_t)n*(OH*OH) + lidx)*BB + tid] = sao[tid];
        else
            aOut[(((size_t)n*BB + tid)*OH + oy)*OH + ox] = sao[tid];
    }
}

// ---------------------------------------------------------------------------
__global__ void reduce_kernel(const float* __restrict__ afc, float* __restrict__ out)
{
    const int t = blockIdx.x*blockDim.x + threadIdx.x;
    if (t < 320) {
        const int n = t / 10, j = t % 10;
        float s = 0.f;
        for (int l = 0; l < 25; l++) s += afc[(n*25 + l)*10 + j];
        out[t] = s * (1.0f/25.0f);
    }
}

// ---------------------------------------------------------------------------
extern "C" void kernel_launch(void* const* d_in, const int* in_sizes, int n_in,
                              void* d_out, int out_size)
{
    const float* x       = (const float*)d_in[0];
    const float* conv1_w = (const float*)d_in[1];
    const float* bn1_g   = (const float*)d_in[2];
    const float* bn1_b   = (const float*)d_in[3];
    const float* conva_w = (const float*)d_in[4];
    const float* bna_g   = (const float*)d_in[5];
    const float* bna_b   = (const float*)d_in[6];
    const float* convp_w = (const float*)d_in[7];
    const float* bnp_g   = (const float*)d_in[8];
    const float* bnp_b   = (const float*)d_in[9];
    const float* W1      = (const float*)d_in[10];
    const float* bu1     = (const float*)d_in[11];
    const float* ba1     = (const float*)d_in[12];
    const float* bnc1_g  = (const float*)d_in[13];
    const float* bnc1_b  = (const float*)d_in[14];
    const float* W2      = (const float*)d_in[15];
    const float* bu2     = (const float*)d_in[16];
    const float* ba2     = (const float*)d_in[17];
    const float* bnc2_g  = (const float*)d_in[18];
    const float* bnc2_b  = (const float*)d_in[19];
    const float* Wfc     = (const float*)d_in[20];
    const float* bufc    = (const float*)d_in[21];
    const float* bafc    = (const float*)d_in[22];

    float *buf1, *bufA, *bufP, *bufA2, *bufP2, *bufA3, *bufP3, *bufFC;
    cudaGetSymbolAddress((void**)&buf1,  g_buf1);
    cudaGetSymbolAddress((void**)&bufA,  g_bufA);
    cudaGetSymbolAddress((void**)&bufP,  g_bufP);
    cudaGetSymbolAddress((void**)&bufA2, g_bufA2);
    cudaGetSymbolAddress((void**)&bufP2, g_bufP2);
    cudaGetSymbolAddress((void**)&bufA3, g_bufA3);
    cudaGetSymbolAddress((void**)&bufP3, g_bufP3);
    cudaGetSymbolAddress((void**)&bufFC, g_bufFC);

    // conv1 + bn
    conv1_kernel<<<dim3(32,16), 224>>>(x, conv1_w, bn1_g, bn1_b, buf1);

    // conva (sigmoid) + convp
    const size_t c3smem = 64*196*sizeof(float);
    cudaFuncSetAttribute(conv3_kernel<true>,  cudaFuncAttributeMaxDynamicSharedMemorySize, (int)c3smem);
    cudaFuncSetAttribute(conv3_kernel<false>, cudaFuncAttributeMaxDynamicSharedMemorySize, (int)c3smem);
    conv3_kernel<true ><<<dim3(32,1),  192, c3smem>>>(buf1, conva_w, bna_g, bna_b, bufA, 256, 16);
    conv3_kernel<false><<<dim3(32,16), 192, c3smem>>>(buf1, convp_w, bnp_g, bnp_b, bufP, 256, 256);

    // Shared-memory size helper (floats):
    //   KKA*VST + 2*BBPS + KSPLIT*BBPS + KKA*SPS + KKA*RST + KKA + 4*BB
    // EM1: 12x12 -> 6x6, k=3 s=2 p=1, A=16 B=16  (bnc1 fused)
    {
        constexpr int KKA = 144, BBPS = 256, VST = 260, RST = 17, SPS = 17, KSP = 4;
        const size_t sm1 = (size_t)(KKA*VST + 2*BBPS + KSP*BBPS + KKA*SPS
                                    + KKA*RST + KKA + 4*16) * sizeof(float);
        auto fn = em_kernel<16,16,16,3,2,1,12,6,KSP,true,false>;
        cudaFuncSetAttribute(fn, cudaFuncAttributeMaxDynamicSharedMemorySize, (int)sm1);
        fn<<<dim3(36,32), 1024, sm1>>>(bufA, bufP, W1, bu1, ba1, bnc1_g, bnc1_b, bufA2, bufP2);
    }

    // EM2: 6x6 -> 6x6, k=3 s=1 p=1, A=16 B=16  (bnc2 fused)
    {
        constexpr int KKA = 144, BBPS = 256, VST = 260, RST = 17, SPS = 17, KSP = 4;
        const size_t sm2 = (size_t)(KKA*VST + 2*BBPS + KSP*BBPS + KKA*SPS
                                    + KKA*RST + KKA + 4*16) * sizeof(float);
        auto fn = em_kernel<16,16,16,3,1,1,6,6,KSP,true,false>;
        cudaFuncSetAttribute(fn, cudaFuncAttributeMaxDynamicSharedMemorySize, (int)sm2);
        fn<<<dim3(36,32), 1024, sm2>>>(bufA2, bufP2, W2, bu2, ba2, bnc2_g, bnc2_b, bufA3, bufP3);
    }

    // EM3 (class caps): 6x6 -> 5x5, k=4 s=1 p=1, A=16 B=10, no pose out
    {
        constexpr int KKA = 256, BBPS = 160, VST = 164, RST = 11, SPS = 17, KSP = 6;
        const size_t sm3 = (size_t)(KKA*VST + 2*BBPS + KSP*BBPS + KKA*SPS
                                    + KKA*RST + KKA + 4*10) * sizeof(float);
        auto fn = em_kernel<16,16,10,4,1,1,6,5,KSP,false,true>;
        cudaFuncSetAttribute(fn, cudaFuncAttributeMaxDynamicSharedMemorySize, (int)sm3);
        fn<<<dim3(25,32), 1024, sm3>>>(bufA3, bufP3, Wfc, bufc, bafc, nullptr, nullptr, bufFC, nullptr);
    }

    // mean over spatial
    reduce_kernel<<<1, 320>>>(bufFC, (float*)d_out);
}

// round 3
// speedup vs baseline: 1.1506x; 1.1506x over previous
#include <cuda_runtime.h>
#include <math.h>
#include <stddef.h>

#define EPSR 1e-8f
// 1/sqrt(1 + 1e-5)
#define BN_SCALE 0.99999500003749969f
#define LOG2PI 1.8378770664093454836f

// ---------------------------------------------------------------------------
// Scratch buffers (device globals; no allocation allowed)
// ---------------------------------------------------------------------------
__device__ float g_buf1 [32*256*14*14];
__device__ float g_bufA [32*16*12*12];
__device__ float g_bufP [32*256*12*12];
__device__ float g_bufA2[32*16*6*6];
__device__ float g_bufP2[32*256*6*6];
__device__ float g_bufA3[32*16*6*6];
__device__ float g_bufP3[32*256*6*6];
__device__ float g_bufFC[32*25*10];

// ---------------------------------------------------------------------------
// conv1: x(32,3,32,32) * w(256,3,5,5) stride2 VALID -> (32,256,14,14), + bn
// ---------------------------------------------------------------------------
__global__ void conv1_kernel(const float* __restrict__ x,
                             const float* __restrict__ w,
                             const float* __restrict__ g,
                             const float* __restrict__ b,
                             float* __restrict__ out)
{
    __shared__ float sIn[3*32*33];
    const int n = blockIdx.x, cot = blockIdx.y;
    const int tid = threadIdx.x;

    for (int idx = tid; idx < 3*32*32; idx += 224) {
        int ci = idx >> 10, rem = idx & 1023, r = rem >> 5, c = rem & 31;
        sIn[(ci*32 + r)*33 + c] = x[n*3072 + idx];
    }
    __syncthreads();

    const int co_l = tid / 14, oy = tid % 14;
    const int co = cot*16 + co_l;

    float acc[14];
#pragma unroll
    for (int i = 0; i < 14; i++) acc[i] = 0.f;

    const float* wp = w + co*75;
#pragma unroll
    for (int ci = 0; ci < 3; ci++) {
#pragma unroll
        for (int kh = 0; kh < 5; kh++) {
            const float* row = sIn + (ci*32 + oy*2 + kh)*33;
#pragma unroll
            for (int kw = 0; kw < 5; kw++) {
                float wv = wp[(ci*5 + kh)*5 + kw];
#pragma unroll
                for (int ox = 0; ox < 14; ox++)
                    acc[ox] = fmaf(wv, row[ox*2 + kw], acc[ox]);
            }
        }
    }
    const float sc = BN_SCALE * g[co], bi = b[co];
    float* op = out + (((size_t)n*256 + co)*14 + oy)*14;
#pragma unroll
    for (int ox = 0; ox < 14; ox++) op[ox] = acc[ox]*sc + bi;
}

// ---------------------------------------------------------------------------
// 3x3 conv over buf1 (N,CI=256,14,14) -> (N,CO,12,12), + bn (+sigmoid)
// ---------------------------------------------------------------------------
template<bool SIG>
__global__ void conv3_kernel(const float* __restrict__ in,
                             const float* __restrict__ w,
                             const float* __restrict__ g,
                             const float* __restrict__ bb,
                             float* __restrict__ out,
                             int CI, int CO)
{
    extern __shared__ float sIn[];   // 64*196
    const int n = blockIdx.x;
    const int tid = threadIdx.x;
    const int co_l = tid / 12, oy = tid % 12;
    const int co = blockIdx.y*16 + co_l;

    float acc[12];
#pragma unroll
    for (int i = 0; i < 12; i++) acc[i] = 0.f;

    for (int ci0 = 0; ci0 < CI; ci0 += 64) {
        __syncthreads();
        for (int idx = tid; idx < 64*196; idx += 192)
            sIn[idx] = in[((size_t)n*CI + ci0)*196 + idx];
        __syncthreads();

        for (int c = 0; c < 64; c++) {
            const float* wp = w + ((size_t)co*CI + ci0 + c)*9;
            float w9[9];
#pragma unroll
            for (int i = 0; i < 9; i++) w9[i] = wp[i];
#pragma unroll
            for (int kh = 0; kh < 3; kh++) {
                const float* row = sIn + (c*14 + oy + kh)*14;
                float rv[14];
#pragma unroll
                for (int i = 0; i < 14; i++) rv[i] = row[i];
#pragma unroll
                for (int kw = 0; kw < 3; kw++) {
                    float wv = w9[kh*3 + kw];
#pragma unroll
                    for (int ox = 0; ox < 12; ox++)
                        acc[ox] = fmaf(wv, rv[ox + kw], acc[ox]);
                }
            }
        }
    }
    const float sc = BN_SCALE * g[co], bi = bb[co];
    float* op = out + (((size_t)n*CO + co)*12 + oy)*12;
#pragma unroll
    for (int ox = 0; ox < 12; ox++) {
        float v = acc[ox]*sc + bi;
        if (SIG) v = 1.0f / (1.0f + expf(-v));
        op[ox] = v;
    }
}

// ---------------------------------------------------------------------------
// EM routing v3: one CTA per (n, l). 1024 threads. Votes in smem.
//   Fused moment pass: one float4 walk of votes computes Sum(c*v), Sum(c*v^2);
//   sigma from moment identity. Coeff computed on the fly (no A2 pass).
//   Phase E: warp-per-k, loop-invariant mu/inv-sigma hoisted to registers.
// ---------------------------------------------------------------------------
template<int A_, int PS, int BB, int KS, int STR, int PD, int IH, int OH,
         int KSPLIT, bool WPOSE, bool FC>
__global__ __launch_bounds__(1024, 1)
void em_kernel(const float* __restrict__ aIn,
               const float* __restrict__ poseIn,
               const float* __restrict__ Wm,    // (KS*KS*A_, BB, 4,4)
               const float* __restrict__ bu,
               const float* __restrict__ ba,
               const float* __restrict__ bng,
               const float* __restrict__ bnb,
               float* __restrict__ aOut,
               float* __restrict__ poseOut)
{
    constexpr int NT   = 1024;
    constexpr int KK   = KS*KS;
    constexpr int KKA  = KK*A_;
    constexpr int BBPS = BB*PS;
    constexpr int VST  = BBPS + 4;       // float4-friendly, conflict-free
    constexpr int RST  = BB + 1;
    constexpr int SPS  = PS + 1;
    constexpr int NV4  = BBPS/4;         // float4 columns
    constexpr int UNITS= KSPLIT*NV4;     // <= 1024
    constexpr int CH   = (KKA + KSPLIT - 1) / KSPLIT;

    extern __shared__ float sm[];
    float* sv   = sm;                    // KKA*VST
    float* pbm  = sv   + KKA*VST;        // KSPLIT*BBPS  (mu partials)
    float* pbs  = pbm  + KSPLIT*BBPS;    // KSPLIT*BBPS  (v^2 partials)
    float* smu  = pbs  + KSPLIT*BBPS;    // BBPS
    float* ssg  = smu  + BBPS;           // BBPS  1/(2 sigma)
    float* slg  = ssg  + BBPS;           // BBPS  log(sigma)
    float* sr   = slg  + BBPS;           // KKA*RST
    float* sa   = sr   + KKA*RST;        // KKA
    float* srs  = sa   + KKA;            // BB  r_sum
    float* sinv = srs  + BB;             // BB  1/(r_sum+eps)
    float* sS   = sinv + BB;             // BB  r_sum/(r_sum+eps)
    float* sao  = sS   + BB;             // BB
    float* sbia = sao  + BB;             // BB
    float* spt  = pbm;                   // KKA*SPS aliased (phase 0 only)

    const int lidx = blockIdx.x;
    const int oy = lidx / OH, ox = lidx % OH;
    const int n  = blockIdx.y;
    const int tid  = threadIdx.x;
    const int wid  = tid >> 5;
    const int lane = tid & 31;

    // ---- Phase 0a: gather pose patch + a_in (zero-padded) ----
    for (int t = tid; t < KKA*PS; t += NT) {
        const int k = t / PS, p = t % PS;
        const int kk = k / A_, ai = k % A_;
        const int ki = kk / KS, kj = kk % KS;
        const int iy = oy*STR + ki - PD, ix = ox*STR + kj - PD;
        float v = 0.f;
        if (iy >= 0 && iy < IH && ix >= 0 && ix < IH)
            v = poseIn[(((size_t)n*A_*PS + ai*PS + p)*IH + iy)*IH + ix];
        spt[k*SPS + p] = v;
    }
    for (int k = tid; k < KKA; k += NT) {
        const int kk = k / A_, ai = k % A_;
        const int ki = kk / KS, kj = kk % KS;
        const int iy = oy*STR + ki - PD, ix = ox*STR + kj - PD;
        float v = 0.f;
        if (iy >= 0 && iy < IH && ix >= 0 && ix < IH)
            v = aIn[(((size_t)n*A_ + ai)*IH + iy)*IH + ix];
        sa[k] = v;
    }
    __syncthreads();

    // ---- Phase 0b: votes v[k][j] = pose4x4 @ W[k][j]; init r = 1/BB ----
    for (int t = tid; t < KKA*BB; t += NT) {
        const int k = t / BB, j = t % BB;
        const float* pm = spt + k*SPS;
        const float* wj = Wm + ((size_t)k*BB + j)*16;
        float* vk = sv + k*VST + j*PS;
#pragma unroll
        for (int xi = 0; xi < 4; xi++) {
            float r0=0.f, r1=0.f, r2=0.f, r3=0.f;
#pragma unroll
            for (int y = 0; y < 4; y++) {
                float a = pm[xi*4 + y];
                r0 = fmaf(a, wj[y*4+0], r0);
                r1 = fmaf(a, wj[y*4+1], r1);
                r2 = fmaf(a, wj[y*4+2], r2);
                r3 = fmaf(a, wj[y*4+3], r3);
            }
            float4 o; o.x=r0; o.y=r1; o.z=r2; o.w=r3;
            *(float4*)(vk + xi*4) = o;
        }
        sr[k*RST + j] = 1.0f / (float)BB;
    }
    __syncthreads();

    float p95 = 1.0f;
    for (int it = 0; it < 3; it++) {
        p95 *= 0.95f;
        const float lam = 0.01f * (1.0f - p95);

        // A: r_sum[j] = sum_k r*a  (warp-per-j, shuffle reduce)
        if (wid < BB) {
            float s = 0.f;
            for (int k = lane; k < KKA; k += 32)
                s = fmaf(sr[k*RST + wid], sa[k], s);
#pragma unroll
            for (int d = 16; d; d >>= 1)
                s += __shfl_xor_sync(0xffffffffu, s, d);
            if (lane == 0) {
                const float inv = 1.0f/(s + EPSR);
                srs[wid] = s; sinv[wid] = inv; sS[wid] = s*inv;
            }
        }
        __syncthreads();

        // BC: fused moment pass over votes (coeff on the fly)
        if (tid < UNITS) {
            const int h = tid / NV4, r4 = tid % NV4;
            const int j = r4 / (PS/4);
            const int k0 = h*CH;
            const int k1 = (k0 + CH < KKA) ? k0 + CH : KKA;
            const float invj = sinv[j];
            float4 m; m.x=m.y=m.z=m.w=0.f;
            float4 s; s.x=s.y=s.z=s.w=0.f;
            for (int k = k0; k < k1; k++) {
                const float c = sr[k*RST + j] * sa[k] * invj;
                const float4 v = *(const float4*)(sv + k*VST + r4*4);
                m.x = fmaf(c, v.x, m.x); s.x = fmaf(c, v.x*v.x, s.x);
                m.y = fmaf(c, v.y, m.y); s.y = fmaf(c, v.y*v.y, s.y);
                m.z = fmaf(c, v.z, m.z); s.z = fmaf(c, v.z*v.z, s.z);
                m.w = fmaf(c, v.w, m.w); s.w = fmaf(c, v.w*v.w, s.w);
            }
            *(float4*)(pbm + h*BBPS + r4*4) = m;
            *(float4*)(pbs + h*BBPS + r4*4) = s;
        }
        __syncthreads();

        // Finalize mu / sigma / logs
        if (tid < BBPS) {
            const int j = tid / PS;
            float m = 0.f, s = 0.f;
#pragma unroll
            for (int h = 0; h < KSPLIT; h++) {
                m += pbm[h*BBPS + tid];
                s += pbs[h*BBPS + tid];
            }
            smu[tid] = m;
            float sg = s - m*m*(2.0f - sS[j]);
            sg = fmaxf(sg, 0.0f) + EPSR;
            slg[tid] = __logf(sg);
            ssg[tid] = 0.5f / sg;
        }
        __syncthreads();

        // D: cost, a_out, softmax bias per j
        if (tid < BB) {
            float sl = 0.f;
#pragma unroll
            for (int p = 0; p < PS; p++) sl += slg[tid*PS + p];
            const float cost = ((float)PS*bu[tid] + 0.5f*sl) * srs[tid];
            const float ao = 1.0f / (1.0f + __expf(-lam*(ba[tid] - cost)));
            sao[tid]  = ao;
            sbia[tid] = -0.5f*((float)PS*LOG2PI + sl) + __logf(ao + EPSR);
        }
        __syncthreads();

        // E: new r  (warp-per-k; lane = h*16 + j; invariants hoisted)
        if (it < 2) {
            const int j = lane & 15, h = lane >> 4;
            const bool act = (j < BB);
            float4 m0, m1, g0, g1;
            float bia = -1e30f;
            if (act) {
                const float* mp = smu + j*PS + h*8;
                const float* gp = ssg + j*PS + h*8;
                m0 = *(const float4*)(mp);   m1 = *(const float4*)(mp+4);
                g0 = *(const float4*)(gp);   g1 = *(const float4*)(gp+4);
                bia = sbia[j];
            }
            for (int k = wid; k < KKA; k += NT/32) {
                float q = 0.f;
                if (act) {
                    const float4* vv = (const float4*)(sv + k*VST + j*PS + h*8);
                    float4 v0 = vv[0], v1 = vv[1];
                    float d;
                    d = v0.x-m0.x; q = fmaf(d*d, g0.x, q);
                    d = v0.y-m0.y; q = fmaf(d*d, g0.y, q);
                    d = v0.z-m0.z; q = fmaf(d*d, g0.z, q);
                    d = v0.w-m0.w; q = fmaf(d*d, g0.w, q);
                    d = v1.x-m1.x; q = fmaf(d*d, g1.x, q);
                    d = v1.y-m1.y; q = fmaf(d*d, g1.y, q);
                    d = v1.z-m1.z; q = fmaf(d*d, g1.z, q);
                    d = v1.w-m1.w; q = fmaf(d*d, g1.w, q);
                }
                q += __shfl_xor_sync(0xffffffffu, q, 16);
                float lnp = act ? bia - q : -1e30f;
                float mx = lnp;
#pragma unroll
                for (int d = 8; d; d >>= 1)
                    mx = fmaxf(mx, __shfl_xor_sync(0xffffffffu, mx, d));
                float e = act ? __expf(lnp - mx) : 0.f;
                float se = e;
#pragma unroll
                for (int d = 8; d; d >>= 1)
                    se += __shfl_xor_sync(0xffffffffu, se, d);
                if (h == 0 && act) sr[k*RST + j] = e / se;
            }
            __syncthreads();
        }
    }
    __syncthreads();

    // Outputs
    if (WPOSE) {
        for (int t = tid; t < BBPS; t += NT) {
            poseOut[(((size_t)n*BBPS + t)*OH + oy)*OH + ox] =
                smu[t]*BN_SCALE*bng[t] + bnb[t];
        }
    }
    if (tid < BB) {
        if (FC)
            aOut[((size_t)n*(OH*OH) + lidx)*BB + tid] = sao[tid];
        else
            aOut[(((size_t)n*BB + tid)*OH + oy)*OH + ox] = sao[tid];
    }
}

// ---------------------------------------------------------------------------
__global__ void reduce_kernel(const float* __restrict__ afc, float* __restrict__ out)
{
    const int t = blockIdx.x*blockDim.x + threadIdx.x;
    if (t < 320) {
        const int n = t / 10, j = t % 10;
        float s = 0.f;
        for (int l = 0; l < 25; l++) s += afc[(n*25 + l)*10 + j];
        out[t] = s * (1.0f/25.0f);
    }
}

// ---------------------------------------------------------------------------
extern "C" void kernel_launch(void* const* d_in, const int* in_sizes, int n_in,
                              void* d_out, int out_size)
{
    const float* x       = (const float*)d_in[0];
    const float* conv1_w = (const float*)d_in[1];
    const float* bn1_g   = (const float*)d_in[2];
    const float* bn1_b   = (const float*)d_in[3];
    const float* conva_w = (const float*)d_in[4];
    const float* bna_g   = (const float*)d_in[5];
    const float* bna_b   = (const float*)d_in[6];
    const float* convp_w = (const float*)d_in[7];
    const float* bnp_g   = (const float*)d_in[8];
    const float* bnp_b   = (const float*)d_in[9];
    const float* W1      = (const float*)d_in[10];
    const float* bu1     = (const float*)d_in[11];
    const float* ba1     = (const float*)d_in[12];
    const float* bnc1_g  = (const float*)d_in[13];
    const float* bnc1_b  = (const float*)d_in[14];
    const float* W2      = (const float*)d_in[15];
    const float* bu2     = (const float*)d_in[16];
    const float* ba2     = (const float*)d_in[17];
    const float* bnc2_g  = (const float*)d_in[18];
    const float* bnc2_b  = (const float*)d_in[19];
    const float* Wfc     = (const float*)d_in[20];
    const float* bufc    = (const float*)d_in[21];
    const float* bafc    = (const float*)d_in[22];

    float *buf1, *bufA, *bufP, *bufA2, *bufP2, *bufA3, *bufP3, *bufFC;
    cudaGetSymbolAddress((void**)&buf1,  g_buf1);
    cudaGetSymbolAddress((void**)&bufA,  g_bufA);
    cudaGetSymbolAddress((void**)&bufP,  g_bufP);
    cudaGetSymbolAddress((void**)&bufA2, g_bufA2);
    cudaGetSymbolAddress((void**)&bufP2, g_bufP2);
    cudaGetSymbolAddress((void**)&bufA3, g_bufA3);
    cudaGetSymbolAddress((void**)&bufP3, g_bufP3);
    cudaGetSymbolAddress((void**)&bufFC, g_bufFC);

    // conv1 + bn
    conv1_kernel<<<dim3(32,16), 224>>>(x, conv1_w, bn1_g, bn1_b, buf1);

    // conva (sigmoid) + convp
    const size_t c3smem = 64*196*sizeof(float);
    cudaFuncSetAttribute(conv3_kernel<true>,  cudaFuncAttributeMaxDynamicSharedMemorySize, (int)c3smem);
    cudaFuncSetAttribute(conv3_kernel<false>, cudaFuncAttributeMaxDynamicSharedMemorySize, (int)c3smem);
    conv3_kernel<true ><<<dim3(32,1),  192, c3smem>>>(buf1, conva_w, bna_g, bna_b, bufA, 256, 16);
    conv3_kernel<false><<<dim3(32,16), 192, c3smem>>>(buf1, convp_w, bnp_g, bnp_b, bufP, 256, 256);

    // smem floats: KKA*VST + 2*KSP*BBPS + 3*BBPS + KKA*RST + KKA + 5*BB
    // EM1: 12x12 -> 6x6, k=3 s=2 p=1, A=16 B=16  (bnc1 fused)
    {
        constexpr int KKA = 144, BBPS = 256, VST = 260, RST = 17, KSP = 16;
        const size_t sm1 = (size_t)(KKA*VST + 2*KSP*BBPS + 3*BBPS
                                    + KKA*RST + KKA + 5*16) * sizeof(float);
        auto fn = em_kernel<16,16,16,3,2,1,12,6,KSP,true,false>;
        cudaFuncSetAttribute(fn, cudaFuncAttributeMaxDynamicSharedMemorySize, (int)sm1);
        fn<<<dim3(36,32), 1024, sm1>>>(bufA, bufP, W1, bu1, ba1, bnc1_g, bnc1_b, bufA2, bufP2);
    }

    // EM2: 6x6 -> 6x6, k=3 s=1 p=1, A=16 B=16  (bnc2 fused)
    {
        constexpr int KKA = 144, BBPS = 256, VST = 260, RST = 17, KSP = 16;
        const size_t sm2 = (size_t)(KKA*VST + 2*KSP*BBPS + 3*BBPS
                                    + KKA*RST + KKA + 5*16) * sizeof(float);
        auto fn = em_kernel<16,16,16,3,1,1,6,6,KSP,true,false>;
        cudaFuncSetAttribute(fn, cudaFuncAttributeMaxDynamicSharedMemorySize, (int)sm2);
        fn<<<dim3(36,32), 1024, sm2>>>(bufA2, bufP2, W2, bu2, ba2, bnc2_g, bnc2_b, bufA3, bufP3);
    }

    // EM3 (class caps): 6x6 -> 5x5, k=4 s=1 p=1, A=16 B=10, no pose out
    {
        constexpr int KKA = 256, BBPS = 160, VST = 164, RST = 11, KSP = 25;
        const size_t sm3 = (size_t)(KKA*VST + 2*KSP*BBPS + 3*BBPS
                                    + KKA*RST + KKA + 5*10) * sizeof(float);
        auto fn = em_kernel<16,16,10,4,1,1,6,5,KSP,false,true>;
        cudaFuncSetAttribute(fn, cudaFuncAttributeMaxDynamicSharedMemorySize, (int)sm3);
        fn<<<dim3(25,32), 1024, sm3>>>(bufA3, bufP3, Wfc, bufc, bafc, nullptr, nullptr, bufFC, nullptr);
    }

    // mean over spatial
    reduce_kernel<<<1, 320>>>(bufFC, (float*)d_out);
}

// round 4
// speedup vs baseline: 1.3229x; 1.1497x over previous
#include <cuda_runtime.h>
#include <math.h>
#include <stddef.h>

#define EPSR 1e-8f
// 1/sqrt(1 + 1e-5)
#define BN_SCALE 0.99999500003749969f
#define LOG2PI 1.8378770664093454836f

// ---------------------------------------------------------------------------
// Scratch buffers (device globals; no allocation allowed)
// ---------------------------------------------------------------------------
__device__ float g_buf1 [32*256*14*14];
__device__ float g_bufA [32*16*12*12];
__device__ float g_bufP [32*256*12*12];
__device__ float g_bufA2[32*16*6*6];
__device__ float g_bufP2[32*256*6*6];
__device__ float g_bufA3[32*16*6*6];
__device__ float g_bufP3[32*256*6*6];
__device__ float g_bufFC[32*25*10];

// ---------------------------------------------------------------------------
// conv1: x(32,3,32,32) * w(256,3,5,5) stride2 VALID -> (32,256,14,14), + bn
// ---------------------------------------------------------------------------
__global__ void conv1_kernel(const float* __restrict__ x,
                             const float* __restrict__ w,
                             const float* __restrict__ g,
                             const float* __restrict__ b,
                             float* __restrict__ out)
{
    __shared__ float sIn[3*32*33];
    const int n = blockIdx.x, cot = blockIdx.y;
    const int tid = threadIdx.x;

    for (int idx = tid; idx < 3*32*32; idx += 224) {
        int ci = idx >> 10, rem = idx & 1023, r = rem >> 5, c = rem & 31;
        sIn[(ci*32 + r)*33 + c] = x[n*3072 + idx];
    }
    __syncthreads();

    const int co_l = tid / 14, oy = tid % 14;
    const int co = cot*16 + co_l;

    float acc[14];
#pragma unroll
    for (int i = 0; i < 14; i++) acc[i] = 0.f;

    const float* wp = w + co*75;
#pragma unroll
    for (int ci = 0; ci < 3; ci++) {
#pragma unroll
        for (int kh = 0; kh < 5; kh++) {
            const float* row = sIn + (ci*32 + oy*2 + kh)*33;
#pragma unroll
            for (int kw = 0; kw < 5; kw++) {
                float wv = wp[(ci*5 + kh)*5 + kw];
#pragma unroll
                for (int ox = 0; ox < 14; ox++)
                    acc[ox] = fmaf(wv, row[ox*2 + kw], acc[ox]);
            }
        }
    }
    const float sc = BN_SCALE * g[co], bi = b[co];
    float* op = out + (((size_t)n*256 + co)*14 + oy)*14;
#pragma unroll
    for (int ox = 0; ox < 14; ox++) op[ox] = acc[ox]*sc + bi;
}

// ---------------------------------------------------------------------------
// 3x3 conv over buf1 (N,CI=256,14,14) -> (N,CO,12,12), + bn (+sigmoid)
// ---------------------------------------------------------------------------
template<bool SIG>
__global__ void conv3_kernel(const float* __restrict__ in,
                             const float* __restrict__ w,
                             const float* __restrict__ g,
                             const float* __restrict__ bb,
                             float* __restrict__ out,
                             int CI, int CO)
{
    extern __shared__ float sIn[];   // 64*196
    const int n = blockIdx.x;
    const int tid = threadIdx.x;
    const int co_l = tid / 12, oy = tid % 12;
    const int co = blockIdx.y*16 + co_l;

    float acc[12];
#pragma unroll
    for (int i = 0; i < 12; i++) acc[i] = 0.f;

    for (int ci0 = 0; ci0 < CI; ci0 += 64) {
        __syncthreads();
        for (int idx = tid; idx < 64*196; idx += 192)
            sIn[idx] = in[((size_t)n*CI + ci0)*196 + idx];
        __syncthreads();

        for (int c = 0; c < 64; c++) {
            const float* wp = w + ((size_t)co*CI + ci0 + c)*9;
            float w9[9];
#pragma unroll
            for (int i = 0; i < 9; i++) w9[i] = wp[i];
#pragma unroll
            for (int kh = 0; kh < 3; kh++) {
                const float* row = sIn + (c*14 + oy + kh)*14;
                float rv[14];
#pragma unroll
                for (int i = 0; i < 14; i++) rv[i] = row[i];
#pragma unroll
                for (int kw = 0; kw < 3; kw++) {
                    float wv = w9[kh*3 + kw];
#pragma unroll
                    for (int ox = 0; ox < 12; ox++)
                        acc[ox] = fmaf(wv, rv[ox + kw], acc[ox]);
                }
            }
        }
    }
    const float sc = BN_SCALE * g[co], bi = bb[co];
    float* op = out + (((size_t)n*CO + co)*12 + oy)*12;
#pragma unroll
    for (int ox = 0; ox < 12; ox++) {
        float v = acc[ox]*sc + bi;
        if (SIG) v = 1.0f / (1.0f + expf(-v));
        op[ox] = v;
    }
}

// ---------------------------------------------------------------------------
// EM routing v4: conflict-free vote walks.
//   Phase 0b: unit=(k,r4) writes one float4 -> consecutive stores.
//   Phase E : warp-per-k, lane reads contiguous float4s (r4=lane, lane+32),
//             j-group shuffle reduce + cross-group softmax.
// ---------------------------------------------------------------------------
template<int A_, int PS, int BB, int KS, int STR, int PD, int IH, int OH,
         int KSPLIT, bool WPOSE, bool FC>
__global__ __launch_bounds__(1024, 1)
void em_kernel(const float* __restrict__ aIn,
               const float* __restrict__ poseIn,
               const float* __restrict__ Wm,    // (KS*KS*A_, BB, 4,4)
               const float* __restrict__ bu,
               const float* __restrict__ ba,
               const float* __restrict__ bng,
               const float* __restrict__ bnb,
               float* __restrict__ aOut,
               float* __restrict__ poseOut)
{
    constexpr int NT   = 1024;
    constexpr int KK   = KS*KS;
    constexpr int KKA  = KK*A_;
    constexpr int BBPS = BB*PS;
    constexpr int VST  = BBPS + 4;       // float4-friendly, conflict-free
    constexpr int RST  = BB + 1;
    constexpr int SPS  = PS + 1;
    constexpr int NV4  = BBPS/4;         // float4 columns per vote row
    constexpr int UNITS= KSPLIT*NV4;     // <= 1024
    constexpr int CH   = (KKA + KSPLIT - 1) / KSPLIT;

    extern __shared__ float sm[];
    float* sv   = sm;                    // KKA*VST
    float* pbm  = sv   + KKA*VST;        // KSPLIT*BBPS  (mu partials)
    float* pbs  = pbm  + KSPLIT*BBPS;    // KSPLIT*BBPS  (v^2 partials)
    float* smu  = pbs  + KSPLIT*BBPS;    // BBPS
    float* ssg  = smu  + BBPS;           // BBPS  1/(2 sigma)
    float* slg  = ssg  + BBPS;           // BBPS  log(sigma)
    float* sr   = slg  + BBPS;           // KKA*RST
    float* sa   = sr   + KKA*RST;        // KKA
    float* srs  = sa   + KKA;            // BB  r_sum
    float* sinv = srs  + BB;             // BB  1/(r_sum+eps)
    float* sS   = sinv + BB;             // BB  r_sum/(r_sum+eps)
    float* sao  = sS   + BB;             // BB
    float* sbia = sao  + BB;             // BB
    float* spt  = pbm;                   // KKA*SPS aliased (phase 0 only)

    const int lidx = blockIdx.x;
    const int oy = lidx / OH, ox = lidx % OH;
    const int n  = blockIdx.y;
    const int tid  = threadIdx.x;
    const int wid  = tid >> 5;
    const int lane = tid & 31;

    // ---- Phase 0a: gather pose patch + a_in (zero-padded) ----
    for (int t = tid; t < KKA*PS; t += NT) {
        const int k = t / PS, p = t % PS;
        const int kk = k / A_, ai = k % A_;
        const int ki = kk / KS, kj = kk % KS;
        const int iy = oy*STR + ki - PD, ix = ox*STR + kj - PD;
        float v = 0.f;
        if (iy >= 0 && iy < IH && ix >= 0 && ix < IH)
            v = poseIn[(((size_t)n*A_*PS + ai*PS + p)*IH + iy)*IH + ix];
        spt[k*SPS + p] = v;
    }
    for (int k = tid; k < KKA; k += NT) {
        const int kk = k / A_, ai = k % A_;
        const int ki = kk / KS, kj = kk % KS;
        const int iy = oy*STR + ki - PD, ix = ox*STR + kj - PD;
        float v = 0.f;
        if (iy >= 0 && iy < IH && ix >= 0 && ix < IH)
            v = aIn[(((size_t)n*A_ + ai)*IH + iy)*IH + ix];
        sa[k] = v;
    }
    __syncthreads();

    // ---- Phase 0b: votes; unit (k, r4=j*4+xi) computes one float4 ----
    for (int t = tid; t < KKA*NV4; t += NT) {
        const int k = t / NV4, r4 = t % NV4;
        const int j = r4 >> 2, xi = r4 & 3;
        const float* pm = spt + k*SPS + xi*4;
        const float* wj = Wm + ((size_t)k*BB + j)*16;
        float r0=0.f, r1=0.f, r2=0.f, r3=0.f;
#pragma unroll
        for (int y = 0; y < 4; y++) {
            float a = pm[y];
            r0 = fmaf(a, wj[y*4+0], r0);
            r1 = fmaf(a, wj[y*4+1], r1);
            r2 = fmaf(a, wj[y*4+2], r2);
            r3 = fmaf(a, wj[y*4+3], r3);
        }
        float4 o; o.x=r0; o.y=r1; o.z=r2; o.w=r3;
        *(float4*)(sv + k*VST + r4*4) = o;
    }
    for (int t = tid; t < KKA*BB; t += NT)
        sr[(t/BB)*RST + (t%BB)] = 1.0f / (float)BB;
    __syncthreads();

    float p95 = 1.0f;
    for (int it = 0; it < 3; it++) {
        p95 *= 0.95f;
        const float lam = 0.01f * (1.0f - p95);

        // A: r_sum[j] = sum_k r*a  (warp-per-j, shuffle reduce)
        if (wid < BB) {
            float s = 0.f;
            for (int k = lane; k < KKA; k += 32)
                s = fmaf(sr[k*RST + wid], sa[k], s);
#pragma unroll
            for (int d = 16; d; d >>= 1)
                s += __shfl_xor_sync(0xffffffffu, s, d);
            if (lane == 0) {
                const float inv = 1.0f/(s + EPSR);
                srs[wid] = s; sinv[wid] = inv; sS[wid] = s*inv;
            }
        }
        __syncthreads();

        // BC: fused moment pass over votes (coeff on the fly)
        if (tid < UNITS) {
            const int h = tid / NV4, r4 = tid % NV4;
            const int j = r4 >> 2;
            const int k0 = h*CH;
            const int k1 = (k0 + CH < KKA) ? k0 + CH : KKA;
            const float invj = sinv[j];
            float4 m; m.x=m.y=m.z=m.w=0.f;
            float4 s; s.x=s.y=s.z=s.w=0.f;
            for (int k = k0; k < k1; k++) {
                const float c = sr[k*RST + j] * sa[k] * invj;
                const float4 v = *(const float4*)(sv + k*VST + r4*4);
                m.x = fmaf(c, v.x, m.x); s.x = fmaf(c, v.x*v.x, s.x);
                m.y = fmaf(c, v.y, m.y); s.y = fmaf(c, v.y*v.y, s.y);
                m.z = fmaf(c, v.z, m.z); s.z = fmaf(c, v.z*v.z, s.z);
                m.w = fmaf(c, v.w, m.w); s.w = fmaf(c, v.w*v.w, s.w);
            }
            *(float4*)(pbm + h*BBPS + r4*4) = m;
            *(float4*)(pbs + h*BBPS + r4*4) = s;
        }
        __syncthreads();

        // Finalize mu / sigma / logs
        if (tid < BBPS) {
            const int j = tid / PS;
            float m = 0.f, s = 0.f;
#pragma unroll
            for (int h = 0; h < KSPLIT; h++) {
                m += pbm[h*BBPS + tid];
                s += pbs[h*BBPS + tid];
            }
            smu[tid] = m;
            float sg = s - m*m*(2.0f - sS[j]);
            sg = fmaxf(sg, 0.0f) + EPSR;
            slg[tid] = __logf(sg);
            ssg[tid] = 0.5f / sg;
        }
        __syncthreads();

        // D: cost, a_out, softmax bias per j
        if (tid < BB) {
            float sl = 0.f;
#pragma unroll
            for (int p = 0; p < PS; p++) sl += slg[tid*PS + p];
            const float cost = ((float)PS*bu[tid] + 0.5f*sl) * srs[tid];
            const float ao = 1.0f / (1.0f + __expf(-lam*(ba[tid] - cost)));
            sao[tid]  = ao;
            sbia[tid] = -0.5f*((float)PS*LOG2PI + sl) + __logf(ao + EPSR);
        }
        __syncthreads();

        // E: new r. Warp-per-k; lane covers r4=lane and r4=lane+32 (contig).
        if (it < 2) {
            const int j1 = lane >> 2;
            const bool act2 = (lane + 32 < NV4);
            const int j2 = (lane + 32) >> 2;
            float4 ma = *(const float4*)(smu + lane*4);
            float4 ga = *(const float4*)(ssg + lane*4);
            const float bia1 = sbia[j1];
            float4 mb, gb; float bia2 = 0.f;
            if (act2) {
                mb = *(const float4*)(smu + (lane+32)*4);
                gb = *(const float4*)(ssg + (lane+32)*4);
                bia2 = sbia[j2];
            }
            for (int k = wid; k < KKA; k += NT/32) {
                const float* vk = sv + k*VST;
                float4 va = *(const float4*)(vk + lane*4);
                float d, qa = 0.f;
                d = va.x-ma.x; qa = fmaf(d*d, ga.x, qa);
                d = va.y-ma.y; qa = fmaf(d*d, ga.y, qa);
                d = va.z-ma.z; qa = fmaf(d*d, ga.z, qa);
                d = va.w-ma.w; qa = fmaf(d*d, ga.w, qa);
                float qb = 0.f;
                if (act2) {
                    float4 vb = *(const float4*)(vk + (lane+32)*4);
                    d = vb.x-mb.x; qb = fmaf(d*d, gb.x, qb);
                    d = vb.y-mb.y; qb = fmaf(d*d, gb.y, qb);
                    d = vb.z-mb.z; qb = fmaf(d*d, gb.z, qb);
                    d = vb.w-mb.w; qb = fmaf(d*d, gb.w, qb);
                }
                // reduce quadform within 4-lane j-group
                qa += __shfl_xor_sync(0xffffffffu, qa, 1);
                qa += __shfl_xor_sync(0xffffffffu, qa, 2);
                qb += __shfl_xor_sync(0xffffffffu, qb, 1);
                qb += __shfl_xor_sync(0xffffffffu, qb, 2);
                const float lnpa = bia1 - qa;
                const float lnpb = act2 ? bia2 - qb : -1e30f;
                // softmax across all j: butterfly over groups (lanes%4 classes
                // each hold one rep per group -> exact max/sum)
                float mx = fmaxf(lnpa, lnpb);
#pragma unroll
                for (int dd = 4; dd <= 16; dd <<= 1)
                    mx = fmaxf(mx, __shfl_xor_sync(0xffffffffu, mx, dd));
                const float ea = __expf(lnpa - mx);
                const float eb = act2 ? __expf(lnpb - mx) : 0.f;
                float se = ea + eb;
#pragma unroll
                for (int dd = 4; dd <= 16; dd <<= 1)
                    se += __shfl_xor_sync(0xffffffffu, se, dd);
                const float inv = 1.0f / se;
                if ((lane & 3) == 0) {
                    sr[k*RST + j1] = ea * inv;
                    if (act2) sr[k*RST + j2] = eb * inv;
                }
            }
            __syncthreads();
        }
    }
    __syncthreads();

    // Outputs
    if (WPOSE) {
        for (int t = tid; t < BBPS; t += NT) {
            poseOut[(((size_t)n*BBPS + t)*OH + oy)*OH + ox] =
                smu[t]*BN_SCALE*bng[t] + bnb[t];
        }
    }
    if (tid < BB) {
        if (FC)
            aOut[((size_t)n*(OH*OH) + lidx)*BB + tid] = sao[tid];
        else
            aOut[(((size_t)n*BB + tid)*OH + oy)*OH + ox] = sao[tid];
    }
}

// ---------------------------------------------------------------------------
__global__ void reduce_kernel(const float* __restrict__ afc, float* __restrict__ out)
{
    const int t = blockIdx.x*blockDim.x + threadIdx.x;
    if (t < 320) {
        const int n = t / 10, j = t % 10;
        float s = 0.f;
        for (int l = 0; l < 25; l++) s += afc[(n*25 + l)*10 + j];
        out[t] = s * (1.0f/25.0f);
    }
}

// ---------------------------------------------------------------------------
extern "C" void kernel_launch(void* const* d_in, const int* in_sizes, int n_in,
                              void* d_out, int out_size)
{
    const float* x       = (const float*)d_in[0];
    const float* conv1_w = (const float*)d_in[1];
    const float* bn1_g   = (const float*)d_in[2];
    const float* bn1_b   = (const float*)d_in[3];
    const float* conva_w = (const float*)d_in[4];
    const float* bna_g   = (const float*)d_in[5];
    const float* bna_b   = (const float*)d_in[6];
    const float* convp_w = (const float*)d_in[7];
    const float* bnp_g   = (const float*)d_in[8];
    const float* bnp_b   = (const float*)d_in[9];
    const float* W1      = (const float*)d_in[10];
    const float* bu1     = (const float*)d_in[11];
    const float* ba1     = (const float*)d_in[12];
    const float* bnc1_g  = (const float*)d_in[13];
    const float* bnc1_b  = (const float*)d_in[14];
    const float* W2      = (const float*)d_in[15];
    const float* bu2     = (const float*)d_in[16];
    const float* ba2     = (const float*)d_in[17];
    const float* bnc2_g  = (const float*)d_in[18];
    const float* bnc2_b  = (const float*)d_in[19];
    const float* Wfc     = (const float*)d_in[20];
    const float* bufc    = (const float*)d_in[21];
    const float* bafc    = (const float*)d_in[22];

    float *buf1, *bufA, *bufP, *bufA2, *bufP2, *bufA3, *bufP3, *bufFC;
    cudaGetSymbolAddress((void**)&buf1,  g_buf1);
    cudaGetSymbolAddress((void**)&bufA,  g_bufA);
    cudaGetSymbolAddress((void**)&bufP,  g_bufP);
    cudaGetSymbolAddress((void**)&bufA2, g_bufA2);
    cudaGetSymbolAddress((void**)&bufP2, g_bufP2);
    cudaGetSymbolAddress((void**)&bufA3, g_bufA3);
    cudaGetSymbolAddress((void**)&bufP3, g_bufP3);
    cudaGetSymbolAddress((void**)&bufFC, g_bufFC);

    // conv1 + bn
    conv1_kernel<<<dim3(32,16), 224>>>(x, conv1_w, bn1_g, bn1_b, buf1);

    // conva (sigmoid) + convp
    const size_t c3smem = 64*196*sizeof(float);
    cudaFuncSetAttribute(conv3_kernel<true>,  cudaFuncAttributeMaxDynamicSharedMemorySize, (int)c3smem);
    cudaFuncSetAttribute(conv3_kernel<false>, cudaFuncAttributeMaxDynamicSharedMemorySize, (int)c3smem);
    conv3_kernel<true ><<<dim3(32,1),  192, c3smem>>>(buf1, conva_w, bna_g, bna_b, bufA, 256, 16);
    conv3_kernel<false><<<dim3(32,16), 192, c3smem>>>(buf1, convp_w, bnp_g, bnp_b, bufP, 256, 256);

    // smem floats: KKA*VST + 2*KSP*BBPS + 3*BBPS + KKA*RST + KKA + 5*BB
    // EM1: 12x12 -> 6x6, k=3 s=2 p=1, A=16 B=16  (bnc1 fused)
    {
        constexpr int KKA = 144, BBPS = 256, VST = 260, RST = 17, KSP = 16;
        const size_t sm1 = (size_t)(KKA*VST + 2*KSP*BBPS + 3*BBPS
                                    + KKA*RST + KKA + 5*16) * sizeof(float);
        auto fn = em_kernel<16,16,16,3,2,1,12,6,KSP,true,false>;
        cudaFuncSetAttribute(fn, cudaFuncAttributeMaxDynamicSharedMemorySize, (int)sm1);
        fn<<<dim3(36,32), 1024, sm1>>>(bufA, bufP, W1, bu1, ba1, bnc1_g, bnc1_b, bufA2, bufP2);
    }

    // EM2: 6x6 -> 6x6, k=3 s=1 p=1, A=16 B=16  (bnc2 fused)
    {
        constexpr int KKA = 144, BBPS = 256, VST = 260, RST = 17, KSP = 16;
        const size_t sm2 = (size_t)(KKA*VST + 2*KSP*BBPS + 3*BBPS
                                    + KKA*RST + KKA + 5*16) * sizeof(float);
        auto fn = em_kernel<16,16,16,3,1,1,6,6,KSP,true,false>;
        cudaFuncSetAttribute(fn, cudaFuncAttributeMaxDynamicSharedMemorySize, (int)sm2);
        fn<<<dim3(36,32), 1024, sm2>>>(bufA2, bufP2, W2, bu2, ba2, bnc2_g, bnc2_b, bufA3, bufP3);
    }

    // EM3 (class caps): 6x6 -> 5x5, k=4 s=1 p=1, A=16 B=10, no pose out
    {
        constexpr int KKA = 256, BBPS = 160, VST = 164, RST = 11, KSP = 25;
        const size_t sm3 = (size_t)(KKA*VST + 2*KSP*BBPS + 3*BBPS
                                    + KKA*RST + KKA + 5*10) * sizeof(float);
        auto fn = em_kernel<16,16,10,4,1,1,6,5,KSP,false,true>;
        cudaFuncSetAttribute(fn, cudaFuncAttributeMaxDynamicSharedMemorySize, (int)sm3);
        fn<<<dim3(25,32), 1024, sm3>>>(bufA3, bufP3, Wfc, bufc, bafc, nullptr, nullptr, bufFC, nullptr);
    }

    // mean over spatial
    reduce_kernel<<<1, 320>>>(bufFC, (float*)d_out);
}

// round 5
// speedup vs baseline: 1.6471x; 1.2451x over previous
#include <cuda_runtime.h>
#include <math.h>
#include <stddef.h>

#define EPSR 1e-8f
// 1/sqrt(1 + 1e-5)
#define BN_SCALE 0.99999500003749969f
#define LOG2PI 1.8378770664093454836f

// ---------------------------------------------------------------------------
// Scratch buffers (device globals; no allocation allowed)
// ---------------------------------------------------------------------------
__device__ float g_buf1 [32*256*14*14];
__device__ float g_bufA [32*16*12*12];
__device__ float g_bufP [32*256*12*12];
__device__ float g_bufA2[32*16*6*6];
__device__ float g_bufP2[32*256*6*6];
__device__ float g_bufA3[32*16*6*6];
__device__ float g_bufP3[32*256*6*6];
__device__ float g_bufFC[32*25*10];

// ---------------------------------------------------------------------------
// conv1: x(32,3,32,32) * w(256,3,5,5) stride2 VALID -> (32,256,14,14), + bn
// ---------------------------------------------------------------------------
__global__ void conv1_kernel(const float* __restrict__ x,
                             const float* __restrict__ w,
                             const float* __restrict__ g,
                             const float* __restrict__ b,
                             float* __restrict__ out)
{
    __shared__ float sIn[3*32*33];
    const int n = blockIdx.x, cot = blockIdx.y;
    const int tid = threadIdx.x;

    for (int idx = tid; idx < 3*32*32; idx += 224) {
        int ci = idx >> 10, rem = idx & 1023, r = rem >> 5, c = rem & 31;
        sIn[(ci*32 + r)*33 + c] = x[n*3072 + idx];
    }
    __syncthreads();

    const int co_l = tid / 14, oy = tid % 14;
    const int co = cot*16 + co_l;

    float acc[14];
#pragma unroll
    for (int i = 0; i < 14; i++) acc[i] = 0.f;

    const float* wp = w + co*75;
#pragma unroll
    for (int ci = 0; ci < 3; ci++) {
#pragma unroll
        for (int kh = 0; kh < 5; kh++) {
            const float* row = sIn + (ci*32 + oy*2 + kh)*33;
#pragma unroll
            for (int kw = 0; kw < 5; kw++) {
                float wv = wp[(ci*5 + kh)*5 + kw];
#pragma unroll
                for (int ox = 0; ox < 14; ox++)
                    acc[ox] = fmaf(wv, row[ox*2 + kw], acc[ox]);
            }
        }
    }
    const float sc = BN_SCALE * g[co], bi = b[co];
    float* op = out + (((size_t)n*256 + co)*14 + oy)*14;
#pragma unroll
    for (int ox = 0; ox < 14; ox++) op[ox] = acc[ox]*sc + bi;
}

// ---------------------------------------------------------------------------
// 3x3 conv over buf1 (N,CI=256,14,14) -> (N,CO,12,12), + bn (+sigmoid)
// NCO output channels per thread (co and co+16).
// ---------------------------------------------------------------------------
template<bool SIG, int NCO>
__global__ void conv3_kernel(const float* __restrict__ in,
                             const float* __restrict__ w,
                             const float* __restrict__ g,
                             const float* __restrict__ bb,
                             float* __restrict__ out,
                             int CI, int CO)
{
    extern __shared__ float sIn[];   // 64*196
    const int n = blockIdx.x;
    const int tid = threadIdx.x;
    const int co_l = tid / 12, oy = tid % 12;
    const int co0 = blockIdx.y*(16*NCO) + co_l;

    float acc[NCO][12];
#pragma unroll
    for (int q = 0; q < NCO; q++)
#pragma unroll
        for (int i = 0; i < 12; i++) acc[q][i] = 0.f;

    for (int ci0 = 0; ci0 < CI; ci0 += 64) {
        __syncthreads();
        for (int idx = tid; idx < 64*196; idx += 192)
            sIn[idx] = in[((size_t)n*CI + ci0)*196 + idx];
        __syncthreads();

        for (int c = 0; c < 64; c++) {
            float w9[NCO][9];
#pragma unroll
            for (int q = 0; q < NCO; q++) {
                const float* wp = w + ((size_t)(co0 + q*16)*CI + ci0 + c)*9;
#pragma unroll
                for (int i = 0; i < 9; i++) w9[q][i] = wp[i];
            }
#pragma unroll
            for (int kh = 0; kh < 3; kh++) {
                const float* row = sIn + (c*14 + oy + kh)*14;
                float rv[14];
#pragma unroll
                for (int i = 0; i < 14; i++) rv[i] = row[i];
#pragma unroll
                for (int kw = 0; kw < 3; kw++) {
#pragma unroll
                    for (int q = 0; q < NCO; q++) {
                        float wv = w9[q][kh*3 + kw];
#pragma unroll
                        for (int ox = 0; ox < 12; ox++)
                            acc[q][ox] = fmaf(wv, rv[ox + kw], acc[q][ox]);
                    }
                }
            }
        }
    }
#pragma unroll
    for (int q = 0; q < NCO; q++) {
        const int co = co0 + q*16;
        const float sc = BN_SCALE * g[co], bi = bb[co];
        float* op = out + (((size_t)n*CO + co)*12 + oy)*12;
#pragma unroll
        for (int ox = 0; ox < 12; ox++) {
            float v = acc[q][ox]*sc + bi;
            if (SIG) v = 1.0f / (1.0f + __expf(-v));
            op[ox] = v;
        }
    }
}

// ---------------------------------------------------------------------------
// EM routing v5: 768 threads (85-reg budget for software pipelining).
//   0b: team-of-4 cooperative W load (LDG.128 + shfl row exchange).
//   BC: fused moments with unrolled/pipelined k-loop.
//   finalize+D merged into warp-per-j phase.
//   E: warp-per-k, contiguous float4 vote reads, shuffle softmax.
// ---------------------------------------------------------------------------
template<int NT, int A_, int PS, int BB, int KS, int STR, int PD, int IH, int OH,
         int KSPLIT, bool WPOSE, bool FC>
__global__ __launch_bounds__(NT, 1)
void em_kernel(const float* __restrict__ aIn,
               const float* __restrict__ poseIn,
               const float* __restrict__ Wm,    // (KS*KS*A_, BB, 4,4)
               const float* __restrict__ bu,
               const float* __restrict__ ba,
               const float* __restrict__ bng,
               const float* __restrict__ bnb,
               float* __restrict__ aOut,
               float* __restrict__ poseOut)
{
    constexpr int KK   = KS*KS;
    constexpr int KKA  = KK*A_;
    constexpr int BBPS = BB*PS;
    constexpr int VST  = BBPS + 4;       // float4-friendly, conflict-free
    constexpr int RST  = BB + 1;
    constexpr int SPS  = PS;             // 16: keeps LDS.128 alignment
    constexpr int NV4  = BBPS/4;
    constexpr int UNITS= KSPLIT*NV4;     // <= NT
    constexpr int CH   = KKA / KSPLIT;   // exact

    extern __shared__ float sm[];
    float* sv   = sm;                    // KKA*VST
    float* pbm  = sv   + KKA*VST;        // KSPLIT*BBPS
    float* pbs  = pbm  + KSPLIT*BBPS;    // KSPLIT*BBPS
    float* smu  = pbs  + KSPLIT*BBPS;    // BBPS
    float* ssg  = smu  + BBPS;           // BBPS  1/(2 sigma)
    float* sr   = ssg  + BBPS;           // KKA*RST
    float* sa   = sr   + KKA*RST;        // KKA
    float* srs  = sa   + KKA;            // BB
    float* sinv = srs  + BB;             // BB
    float* sS   = sinv + BB;             // BB
    float* sao  = sS   + BB;             // BB
    float* sbia = sao  + BB;             // BB
    float* spt  = pbm;                   // KKA*SPS aliased (phase 0 only)

    const int lidx = blockIdx.x;
    const int oy = lidx / OH, ox = lidx % OH;
    const int n  = blockIdx.y;
    const int tid  = threadIdx.x;
    const int wid  = tid >> 5;
    const int lane = tid & 31;

    // ---- Phase 0a: gather pose patch + a_in (zero-padded) ----
    for (int t = tid; t < KKA*PS; t += NT) {
        const int k = t / PS, p = t % PS;
        const int kk = k / A_, ai = k % A_;
        const int ki = kk / KS, kj = kk % KS;
        const int iy = oy*STR + ki - PD, ix = ox*STR + kj - PD;
        float v = 0.f;
        if (iy >= 0 && iy < IH && ix >= 0 && ix < IH)
            v = poseIn[(((size_t)n*A_*PS + ai*PS + p)*IH + iy)*IH + ix];
        spt[k*SPS + p] = v;
    }
    for (int k = tid; k < KKA; k += NT) {
        const int kk = k / A_, ai = k % A_;
        const int ki = kk / KS, kj = kk % KS;
        const int iy = oy*STR + ki - PD, ix = ox*STR + kj - PD;
        float v = 0.f;
        if (iy >= 0 && iy < IH && ix >= 0 && ix < IH)
            v = aIn[(((size_t)n*A_ + ai)*IH + iy)*IH + ix];
        sa[k] = v;
    }
    __syncthreads();

    // ---- Phase 0b: votes; team-of-4 cooperative (k, j) unit ----
    {
        constexpr int TOT = KKA*NV4;
        constexpr int TRIPS = (TOT + NT - 1) / NT;
#pragma unroll
        for (int tr = 0; tr < TRIPS; tr++) {
            const int t = tr*NT + tid;
            const bool act = (t < TOT);
            const int k = act ? t / NV4 : 0;
            const int r4 = act ? t % NV4 : 0;
            const int j = r4 >> 2, xi = lane & 3;   // xi == r4 & 3 (aligned)
            float4 p4 = make_float4(0,0,0,0), w4 = make_float4(0,0,0,0);
            if (act) {
                p4 = *(const float4*)(spt + k*SPS + xi*4);
                w4 = *(const float4*)(Wm + ((size_t)k*BB + j)*16 + xi*4);
            }
            float4 acc; acc.x = acc.y = acc.z = acc.w = 0.f;
            const int base = lane & ~3;
#pragma unroll
            for (int y = 0; y < 4; y++) {
                const float py = (y==0) ? p4.x : (y==1) ? p4.y : (y==2) ? p4.z : p4.w;
                float4 wy;
                wy.x = __shfl_sync(0xffffffffu, w4.x, base + y);
                wy.y = __shfl_sync(0xffffffffu, w4.y, base + y);
                wy.z = __shfl_sync(0xffffffffu, w4.z, base + y);
                wy.w = __shfl_sync(0xffffffffu, w4.w, base + y);
                acc.x = fmaf(py, wy.x, acc.x);
                acc.y = fmaf(py, wy.y, acc.y);
                acc.z = fmaf(py, wy.z, acc.z);
                acc.w = fmaf(py, wy.w, acc.w);
            }
            if (act) *(float4*)(sv + k*VST + r4*4) = acc;
        }
    }
    for (int t = tid; t < KKA*BB; t += NT)
        sr[(t/BB)*RST + (t%BB)] = 1.0f / (float)BB;
    __syncthreads();

    float p95 = 1.0f;
    for (int it = 0; it < 3; it++) {
        p95 *= 0.95f;
        const float lam = 0.01f * (1.0f - p95);

        // A: r_sum[j] = sum_k r*a  (warp-per-j, shuffle reduce)
        if (wid < BB) {
            float s = 0.f;
            for (int k = lane; k < KKA; k += 32)
                s = fmaf(sr[k*RST + wid], sa[k], s);
#pragma unroll
            for (int d = 16; d; d >>= 1)
                s += __shfl_xor_sync(0xffffffffu, s, d);
            if (lane == 0) {
                const float inv = 1.0f/(s + EPSR);
                srs[wid] = s; sinv[wid] = inv; sS[wid] = s*inv;
            }
        }
        __syncthreads();

        // BC: fused moment pass over votes (coeff on the fly), pipelined
        if (tid < UNITS) {
            const int h = tid / NV4, r4 = tid % NV4;
            const int j = r4 >> 2;
            const int k0 = h*CH;
            const float invj = sinv[j];
            float4 m; m.x=m.y=m.z=m.w=0.f;
            float4 s; s.x=s.y=s.z=s.w=0.f;
#pragma unroll 4
            for (int i = 0; i < CH; i++) {
                const int k = k0 + i;
                const float c = sr[k*RST + j] * sa[k] * invj;
                const float4 v = *(const float4*)(sv + k*VST + r4*4);
                m.x = fmaf(c, v.x, m.x); s.x = fmaf(c, v.x*v.x, s.x);
                m.y = fmaf(c, v.y, m.y); s.y = fmaf(c, v.y*v.y, s.y);
                m.z = fmaf(c, v.z, m.z); s.z = fmaf(c, v.z*v.z, s.z);
                m.w = fmaf(c, v.w, m.w); s.w = fmaf(c, v.w*v.w, s.w);
            }
            *(float4*)(pbm + h*BBPS + r4*4) = m;
            *(float4*)(pbs + h*BBPS + r4*4) = s;
        }
        __syncthreads();

        // Finalize + D merged: warp j reduces partials, computes
        // mu/sigma/logs and (lane 0) cost, a_out, softmax bias.
        if (wid < BB) {
            const int j = wid;
            float lg = 0.f;
            if (lane < PS) {
                const int idx = j*PS + lane;
                float m = 0.f, s = 0.f;
#pragma unroll
                for (int h = 0; h < KSPLIT; h++) {
                    m += pbm[h*BBPS + idx];
                    s += pbs[h*BBPS + idx];
                }
                smu[idx] = m;
                float sg = fmaxf(s - m*m*(2.0f - sS[j]), 0.0f) + EPSR;
                ssg[idx] = 0.5f / sg;
                lg = __logf(sg);
            }
            float sl = lg;
#pragma unroll
            for (int d = 16; d; d >>= 1)
                sl += __shfl_xor_sync(0xffffffffu, sl, d);
            if (lane == 0) {
                const float cost = ((float)PS*bu[j] + 0.5f*sl) * srs[j];
                const float ao = 1.0f / (1.0f + __expf(-lam*(ba[j] - cost)));
                sao[j]  = ao;
                sbia[j] = -0.5f*((float)PS*LOG2PI + sl) + __logf(ao + EPSR);
            }
        }
        __syncthreads();

        // E: new r. Warp-per-k; lane covers r4=lane and r4=lane+32 (contig).
        if (it < 2) {
            const int j1 = lane >> 2;
            const bool act2 = (lane + 32 < NV4);
            const int j2 = (lane + 32) >> 2;
            float4 ma = *(const float4*)(smu + lane*4);
            float4 ga = *(const float4*)(ssg + lane*4);
            const float bia1 = sbia[j1];
            float4 mb, gb; float bia2 = 0.f;
            if (act2) {
                mb = *(const float4*)(smu + (lane+32)*4);
                gb = *(const float4*)(ssg + (lane+32)*4);
                bia2 = sbia[j2];
            }
#pragma unroll 2
            for (int k = wid; k < KKA; k += NT/32) {
                const float* vk = sv + k*VST;
                float4 va = *(const float4*)(vk + lane*4);
                float d, qa = 0.f;
                d = va.x-ma.x; qa = fmaf(d*d, ga.x, qa);
                d = va.y-ma.y; qa = fmaf(d*d, ga.y, qa);
                d = va.z-ma.z; qa = fmaf(d*d, ga.z, qa);
                d = va.w-ma.w; qa = fmaf(d*d, ga.w, qa);
                float qb = 0.f;
                if (act2) {
                    float4 vb = *(const float4*)(vk + (lane+32)*4);
                    d = vb.x-mb.x; qb = fmaf(d*d, gb.x, qb);
                    d = vb.y-mb.y; qb = fmaf(d*d, gb.y, qb);
                    d = vb.z-mb.z; qb = fmaf(d*d, gb.z, qb);
                    d = vb.w-mb.w; qb = fmaf(d*d, gb.w, qb);
                }
                qa += __shfl_xor_sync(0xffffffffu, qa, 1);
                qa += __shfl_xor_sync(0xffffffffu, qa, 2);
                qb += __shfl_xor_sync(0xffffffffu, qb, 1);
                qb += __shfl_xor_sync(0xffffffffu, qb, 2);
                const float lnpa = bia1 - qa;
                const float lnpb = act2 ? bia2 - qb : -1e30f;
                float mx = fmaxf(lnpa, lnpb);
#pragma unroll
                for (int dd = 4; dd <= 16; dd <<= 1)
                    mx = fmaxf(mx, __shfl_xor_sync(0xffffffffu, mx, dd));
                const float ea = __expf(lnpa - mx);
                const float eb = act2 ? __expf(lnpb - mx) : 0.f;
                float se = ea + eb;
#pragma unroll
                for (int dd = 4; dd <= 16; dd <<= 1)
                    se += __shfl_xor_sync(0xffffffffu, se, dd);
                const float inv = 1.0f / se;
                if ((lane & 3) == 0) {
                    sr[k*RST + j1] = ea * inv;
                    if (act2) sr[k*RST + j2] = eb * inv;
                }
            }
            __syncthreads();
        }
    }
    __syncthreads();

    // Outputs
    if (WPOSE) {
        for (int t = tid; t < BBPS; t += NT) {
            poseOut[(((size_t)n*BBPS + t)*OH + oy)*OH + ox] =
                smu[t]*BN_SCALE*bng[t] + bnb[t];
        }
    }
    if (tid < BB) {
        if (FC)
            aOut[((size_t)n*(OH*OH) + lidx)*BB + tid] = sao[tid];
        else
            aOut[(((size_t)n*BB + tid)*OH + oy)*OH + ox] = sao[tid];
    }
}

// ---------------------------------------------------------------------------
__global__ void reduce_kernel(const float* __restrict__ afc, float* __restrict__ out)
{
    const int t = blockIdx.x*blockDim.x + threadIdx.x;
    if (t < 320) {
        const int n = t / 10, j = t % 10;
        float s = 0.f;
        for (int l = 0; l < 25; l++) s += afc[(n*25 + l)*10 + j];
        out[t] = s * (1.0f/25.0f);
    }
}

// ---------------------------------------------------------------------------
extern "C" void kernel_launch(void* const* d_in, const int* in_sizes, int n_in,
                              void* d_out, int out_size)
{
    const float* x       = (const float*)d_in[0];
    const float* conv1_w = (const float*)d_in[1];
    const float* bn1_g   = (const float*)d_in[2];
    const float* bn1_b   = (const float*)d_in[3];
    const float* conva_w = (const float*)d_in[4];
    const float* bna_g   = (const float*)d_in[5];
    const float* bna_b   = (const float*)d_in[6];
    const float* convp_w = (const float*)d_in[7];
    const float* bnp_g   = (const float*)d_in[8];
    const float* bnp_b   = (const float*)d_in[9];
    const float* W1      = (const float*)d_in[10];
    const float* bu1     = (const float*)d_in[11];
    const float* ba1     = (const float*)d_in[12];
    const float* bnc1_g  = (const float*)d_in[13];
    const float* bnc1_b  = (const float*)d_in[14];
    const float* W2      = (const float*)d_in[15];
    const float* bu2     = (const float*)d_in[16];
    const float* ba2     = (const float*)d_in[17];
    const float* bnc2_g  = (const float*)d_in[18];
    const float* bnc2_b  = (const float*)d_in[19];
    const float* Wfc     = (const float*)d_in[20];
    const float* bufc    = (const float*)d_in[21];
    const float* bafc    = (const float*)d_in[22];

    float *buf1, *bufA, *bufP, *bufA2, *bufP2, *bufA3, *bufP3, *bufFC;
    cudaGetSymbolAddress((void**)&buf1,  g_buf1);
    cudaGetSymbolAddress((void**)&bufA,  g_bufA);
    cudaGetSymbolAddress((void**)&bufP,  g_bufP);
    cudaGetSymbolAddress((void**)&bufA2, g_bufA2);
    cudaGetSymbolAddress((void**)&bufP2, g_bufP2);
    cudaGetSymbolAddress((void**)&bufA3, g_bufA3);
    cudaGetSymbolAddress((void**)&bufP3, g_bufP3);
    cudaGetSymbolAddress((void**)&bufFC, g_bufFC);

    // conv1 + bn
    conv1_kernel<<<dim3(32,16), 224>>>(x, conv1_w, bn1_g, bn1_b, buf1);

    // conva (sigmoid, 1 co/thread) + convp (2 co/thread)
    const size_t c3smem = 64*196*sizeof(float);
    cudaFuncSetAttribute((const void*)conv3_kernel<true,1>,  cudaFuncAttributeMaxDynamicSharedMemorySize, (int)c3smem);
    cudaFuncSetAttribute((const void*)conv3_kernel<false,2>, cudaFuncAttributeMaxDynamicSharedMemorySize, (int)c3smem);
    conv3_kernel<true,1 ><<<dim3(32,1), 192, c3smem>>>(buf1, conva_w, bna_g, bna_b, bufA, 256, 16);
    conv3_kernel<false,2><<<dim3(32,8), 192, c3smem>>>(buf1, convp_w, bnp_g, bnp_b, bufP, 256, 256);

    // smem floats: KKA*VST + 2*KSP*BBPS + 2*BBPS + KKA*RST + KKA + 5*BB
    // EM1: 12x12 -> 6x6, k=3 s=2 p=1, A=16 B=16  (bnc1 fused)
    {
        constexpr int KKA = 144, BBPS = 256, VST = 260, RST = 17, KSP = 12;
        const size_t sm1 = (size_t)(KKA*VST + 2*KSP*BBPS + 2*BBPS
                                    + KKA*RST + KKA + 5*16) * sizeof(float);
        auto fn = em_kernel<768,16,16,16,3,2,1,12,6,KSP,true,false>;
        cudaFuncSetAttribute(fn, cudaFuncAttributeMaxDynamicSharedMemorySize, (int)sm1);
        fn<<<dim3(36,32), 768, sm1>>>(bufA, bufP, W1, bu1, ba1, bnc1_g, bnc1_b, bufA2, bufP2);
    }

    // EM2: 6x6 -> 6x6, k=3 s=1 p=1, A=16 B=16  (bnc2 fused)
    {
        constexpr int KKA = 144, BBPS = 256, VST = 260, RST = 17, KSP = 12;
        const size_t sm2 = (size_t)(KKA*VST + 2*KSP*BBPS + 2*BBPS
                                    + KKA*RST + KKA + 5*16) * sizeof(float);
        auto fn = em_kernel<768,16,16,16,3,1,1,6,6,KSP,true,false>;
        cudaFuncSetAttribute(fn, cudaFuncAttributeMaxDynamicSharedMemorySize, (int)sm2);
        fn<<<dim3(36,32), 768, sm2>>>(bufA2, bufP2, W2, bu2, ba2, bnc2_g, bnc2_b, bufA3, bufP3);
    }

    // EM3 (class caps): 6x6 -> 5x5, k=4 s=1 p=1, A=16 B=10, no pose out
    {
        constexpr int KKA = 256, BBPS = 160, VST = 164, RST = 11, KSP = 16;
        const size_t sm3 = (size_t)(KKA*VST + 2*KSP*BBPS + 2*BBPS
                                    + KKA*RST + KKA + 5*10) * sizeof(float);
        auto fn = em_kernel<768,16,16,10,4,1,1,6,5,KSP,false,true>;
        cudaFuncSetAttribute(fn, cudaFuncAttributeMaxDynamicSharedMemorySize, (int)sm3);
        fn<<<dim3(25,32), 768, sm3>>>(bufA3, bufP3, Wfc, bufc, bafc, nullptr, nullptr, bufFC, nullptr);
    }

    // mean over spatial
    reduce_kernel<<<1, 320>>>(bufFC, (float*)d_out);
}